// round 14
// baseline (speedup 1.0000x reference)
#include <cuda_runtime.h>
#include <cuda_bf16.h>

// x  : (1, 64, 28, 28) fp32 -> (2 groups o, 32 ch j, 28 n, 28 m)
// w1 : (128, 9),  w2 : (32, 7, 9)
// out: (1, 256, 28, 28), channel = o*128 + c, rolled +1 along height.
//
// t4[o,n,m,i]         = sum_{j,k} x[o*32+j, n, m+k-3] * w2[j,k,i]
// out[o,c,(n+1)%28,m] = sum_i w1[c,i] * t4[o,n,m,i]
//
// Grid 112 = (og, n, m-half), 288 threads. t4 warp = i, lane = (q, m-pair).
// NEW vs R13: w2 never touches smem — each thread __ldg's its 56 weights
// into registers at entry (latency hidden under x staging + barrier).
// Staging is x-only; t4 is pure x-LDS + FMA. Shuffle reduce; 2 barriers.

#define NTHREADS 288

__global__ __launch_bounds__(NTHREADS)
void fused_unfold_einsum_kernel(const float* __restrict__ x,
                                const float* __restrict__ w1,
                                const float* __restrict__ w2,
                                float* __restrict__ out) {
    __shared__ __align__(16) float xs[32][20];   // 14-wide half tile + 3 halo
    __shared__ __align__(16) float t4s[14 * 12]; // [m_local][i], stride 12

    const int tid    = threadIdx.x;
    const int b      = blockIdx.x;      // 0..111
    const int og     = b / 56;
    const int r      = b - og * 56;
    const int n      = r >> 1;
    const int mh     = r & 1;
    const int m_base = mh * 14;

    const int i    = tid >> 5;          // warp id = i (0..8)
    const int lane = tid & 31;
    const int lq   = lane / 7;
    const int q    = lq & 3;            // lanes 28..31 -> q=0 (dup, discarded)
    const int mp   = lane - lq * 7;     // 0..6
    const int m0   = mp * 2;            // even -> 8B-aligned xs reads

    // --- Prefetch this thread's 56 t4 weights to registers:
    //     wreg[jj][k] = w2[(row*7+k)*9 + i], row = q + 4*jj.
    //     56 independent LDGs; latency hidden under x staging + barrier.
    float wreg[8][7];
    #pragma unroll
    for (int jj = 0; jj < 8; ++jj) {
        const int base = (q + 4 * jj) * 63 + i;     // (row*7+0)*9 + i
        #pragma unroll
        for (int k = 0; k < 7; ++k)
            wreg[jj][k] = __ldg(&w2[base + k * 9]);
    }

    // --- Prefetch this thread's w1 row to registers (phase 2).
    const int c    = tid & 127;
    const int mseg = (tid >> 7) & 1;
    float w1r[9];
    #pragma unroll
    for (int ii = 0; ii < 9; ++ii)
        w1r[ii] = __ldg(&w1[c * 9 + ii]);

    // --- Stage x half-row slab with zero halo: cols = m_base-3 .. m_base+16
    #pragma unroll
    for (int idx = tid; idx < 32 * 20; idx += NTHREADS) {
        const int j   = idx / 20;
        const int col = idx - j * 20;
        const int m   = m_base - 3 + col;
        float v = 0.0f;
        if (m >= 0 && m < 28)
            v = x[((og * 32 + j) * 28 + n) * 28 + m];
        xs[j][col] = v;
    }
    __syncthreads();

    // --- t4: pure x-LDS + FMA; weights already in registers.
    {
        float r0 = 0.f, r1 = 0.f;
        #pragma unroll
        for (int jj = 0; jj < 8; ++jj) {
            const int row = q + 4 * jj;
            const float2* __restrict__ xp =
                reinterpret_cast<const float2*>(&xs[row][m0]);
            const float2 p0 = xp[0], p1 = xp[1], p2 = xp[2], p3 = xp[3];
            const float px0 = p0.x, px1 = p0.y, px2 = p1.x, px3 = p1.y;
            const float px4 = p2.x, px5 = p2.y, px6 = p3.x, px7 = p3.y;
            r0 = fmaf(px0, wreg[jj][0], r0);  r1 = fmaf(px1, wreg[jj][0], r1);
            r0 = fmaf(px1, wreg[jj][1], r0);  r1 = fmaf(px2, wreg[jj][1], r1);
            r0 = fmaf(px2, wreg[jj][2], r0);  r1 = fmaf(px3, wreg[jj][2], r1);
            r0 = fmaf(px3, wreg[jj][3], r0);  r1 = fmaf(px4, wreg[jj][3], r1);
            r0 = fmaf(px4, wreg[jj][4], r0);  r1 = fmaf(px5, wreg[jj][4], r1);
            r0 = fmaf(px5, wreg[jj][5], r0);  r1 = fmaf(px6, wreg[jj][5], r1);
            r0 = fmaf(px6, wreg[jj][6], r0);  r1 = fmaf(px7, wreg[jj][6], r1);
        }
        // Reduce the 4 quarters (lanes q*7+mp): +14 then +7.
        r0 += __shfl_down_sync(0xFFFFFFFFu, r0, 14);
        r1 += __shfl_down_sync(0xFFFFFFFFu, r1, 14);
        r0 += __shfl_down_sync(0xFFFFFFFFu, r0, 7);
        r1 += __shfl_down_sync(0xFFFFFFFFu, r1, 7);
        if (lane < 7) {                 // q==0 lanes hold the full sums
            t4s[(m0 + 0) * 12 + i] = r0;
            t4s[(m0 + 1) * 12 + i] = r1;
        }
    }
    __syncthreads();

    // --- Phase 2 (threads 0..255): c-major, w1 in regs, t4s via broadcast
    //     LDS.128, 2 m's per 8B-aligned STG.64.
    if (tid < 256) {
        const int nout   = (n + 1) % 28;    // jnp.roll(y, +1, axis=2)
        const int mstart = mseg ? 8 : 0;
        const int ngrp   = mseg ? 3 : 4;
        float* __restrict__ orow =
            &out[((og * 128 + c) * 28 + nout) * 28 + m_base];

        #pragma unroll
        for (int gp = 0; gp < 4; ++gp) {
            if (gp < ngrp) {                // warp-uniform predicate
                float o2[2];
                #pragma unroll
                for (int qq = 0; qq < 2; ++qq) {
                    const int m = mstart + gp * 2 + qq;
                    const float4* __restrict__ tv =
                        reinterpret_cast<const float4*>(&t4s[m * 12]);
                    const float4 v0 = tv[0], v1 = tv[1], v2 = tv[2];
                    float acc = v0.x * w1r[0];
                    acc = fmaf(v0.y, w1r[1], acc);
                    acc = fmaf(v0.z, w1r[2], acc);
                    acc = fmaf(v0.w, w1r[3], acc);
                    acc = fmaf(v1.x, w1r[4], acc);
                    acc = fmaf(v1.y, w1r[5], acc);
                    acc = fmaf(v1.z, w1r[6], acc);
                    acc = fmaf(v1.w, w1r[7], acc);
                    acc = fmaf(v2.x, w1r[8], acc);
                    o2[qq] = acc;
                }
                *reinterpret_cast<float2*>(&orow[mstart + gp * 2]) =
                    make_float2(o2[0], o2[1]);
            }
        }
    }
}

extern "C" void kernel_launch(void* const* d_in, const int* in_sizes, int n_in,
                              void* d_out, int out_size) {
    const float* x  = (const float*)d_in[0];
    const float* w1 = (const float*)d_in[1];
    const float* w2 = (const float*)d_in[2];
    float* out = (float*)d_out;
    (void)in_sizes; (void)n_in; (void)out_size;

    fused_unfold_einsum_kernel<<<112, NTHREADS>>>(x, w1, w2, out);
}